// round 3
// baseline (speedup 1.0000x reference)
#include <cuda_runtime.h>
#include <math.h>

#define LEVELS 16
#define TABLE_SIZE 524288
#define HMASK (TABLE_SIZE - 1)
#define NPTS 1048576
#define PRIME 2654435761u
#define THREADS 256
#define NBUCKETS 65536           // 256 x 256 Morton buckets, ~16 pts each
#define SCAN_THREADS 1024
#define PER_SCAN (NBUCKETS / SCAN_THREADS)

struct ResArr { float r[LEVELS]; };

// Scratch (no allocation allowed; __device__ globals are the sanctioned path)
__device__ int    d_hist[NBUCKETS];
__device__ int    d_offs[NBUCKETS];
__device__ int    d_perm[NPTS];
__device__ float2 d_sxy[NPTS];

__device__ __forceinline__ unsigned expand8(unsigned v) {
    v = (v | (v << 4)) & 0x0F0Fu;
    v = (v | (v << 2)) & 0x3333u;
    v = (v | (v << 1)) & 0x5555u;
    return v;
}
__device__ __forceinline__ unsigned bucket_of(float2 p) {
    unsigned bx = (unsigned)(int)(p.x * 256.0f);
    unsigned by = (unsigned)(int)(p.y * 256.0f);
    bx = bx > 255u ? 255u : bx;
    by = by > 255u ? 255u : by;
    return expand8(bx) | (expand8(by) << 1);
}

__global__ void zero_hist_kernel() {
    int i = blockIdx.x * blockDim.x + threadIdx.x;
    if (i < NBUCKETS) d_hist[i] = 0;
}

__global__ __launch_bounds__(THREADS)
void hist_kernel(const float2* __restrict__ x) {
    int i = blockIdx.x * blockDim.x + threadIdx.x;
    atomicAdd(&d_hist[bucket_of(x[i])], 1);
}

__global__ __launch_bounds__(SCAN_THREADS)
void scan_kernel() {
    __shared__ int part[SCAN_THREADS];
    int t = threadIdx.x;
    int base = t * PER_SCAN;
    int s = 0;
#pragma unroll
    for (int i = 0; i < PER_SCAN; ++i) s += d_hist[base + i];
    part[t] = s;
    __syncthreads();
    // Hillis-Steele inclusive scan
    for (int off = 1; off < SCAN_THREADS; off <<= 1) {
        int v = (t >= off) ? part[t - off] : 0;
        __syncthreads();
        part[t] += v;
        __syncthreads();
    }
    int run = (t == 0) ? 0 : part[t - 1];   // exclusive prefix
#pragma unroll
    for (int i = 0; i < PER_SCAN; ++i) {
        int c = d_hist[base + i];
        d_offs[base + i] = run;
        run += c;
    }
}

__global__ __launch_bounds__(THREADS)
void scatter_kernel(const float2* __restrict__ x) {
    int i = blockIdx.x * blockDim.x + threadIdx.x;
    float2 p = x[i];
    int pos = atomicAdd(&d_offs[bucket_of(p)], 1);
    d_perm[pos] = i;
    d_sxy[pos] = p;
}

__device__ __forceinline__ void level_gather(
    const float2* __restrict__ t, float r, float px, float py,
    float& a0, float& a1)
{
    float sx = px * r;
    float sy = py * r;
    float gxf = floorf(sx);
    float gyf = floorf(sy);
    float fx = sx - gxf;
    float fy = sy - gyf;
    float ox = 1.0f - fx;
    float oy = 1.0f - fy;

    unsigned gx = (unsigned)(int)gxf;
    unsigned gy = (unsigned)(int)gyf;
    unsigned hy0 = gy * PRIME;
    unsigned hy1 = hy0 + PRIME;

    unsigned i00 = ( gx       ^ hy0) & HMASK;
    unsigned i01 = ( gx       ^ hy1) & HMASK;
    unsigned i10 = ((gx + 1u) ^ hy0) & HMASK;
    unsigned i11 = ((gx + 1u) ^ hy1) & HMASK;

    const float4* t4 = reinterpret_cast<const float4*>(t);
    float4 q0 = __ldg(t4 + (i00 >> 1));   // entries {i00&~1, i00|1}
    float4 q1 = __ldg(t4 + (i01 >> 1));

    bool hi0 = (i00 & 1u) != 0u;
    bool hi1 = (i01 & 1u) != 0u;

    float2 f00 = hi0 ? make_float2(q0.z, q0.w) : make_float2(q0.x, q0.y);
    float2 f01 = hi1 ? make_float2(q1.z, q1.w) : make_float2(q1.x, q1.y);
    float2 f10 = hi0 ? make_float2(q0.x, q0.y) : make_float2(q0.z, q0.w);
    float2 f11 = hi1 ? make_float2(q1.x, q1.y) : make_float2(q1.z, q1.w);

    if (gx & 1u) {   // odd gx: x+1 corner is not the pair partner
        f10 = __ldg(t + i10);
        f11 = __ldg(t + i11);
    }

    float w00 = fx * fy;
    float w10 = ox * fy;
    float w01 = fx * oy;
    float w11 = ox * oy;

    a0 = (w00 * f00.x + w10 * f10.x) + (w01 * f01.x + w11 * f11.x);
    a1 = (w00 * f00.y + w10 * f10.y) + (w01 * f01.y + w11 * f11.y);
}

__global__ __launch_bounds__(THREADS)
void hashenc_kernel(const float2* __restrict__ tables,
                    float* __restrict__ out,
                    ResArr res)
{
    int j = blockIdx.x * blockDim.x + threadIdx.x;
    float2 p = d_sxy[j];
    int n = d_perm[j];

    float acc0[LEVELS];
    float acc1[LEVELS];

#pragma unroll
    for (int l = 0; l < LEVELS; ++l) {
        const float2* t = tables + (size_t)l * TABLE_SIZE;
        level_gather(t, res.r[l], p.x, p.y, acc0[l], acc1[l]);
    }

    float4* o = reinterpret_cast<float4*>(out + (size_t)n * (2 * LEVELS));
#pragma unroll
    for (int i = 0; i < 4; ++i)
        o[i] = make_float4(acc0[4*i], acc0[4*i+1], acc0[4*i+2], acc0[4*i+3]);
#pragma unroll
    for (int i = 0; i < 4; ++i)
        o[4 + i] = make_float4(acc1[4*i], acc1[4*i+1], acc1[4*i+2], acc1[4*i+3]);
}

extern "C" void kernel_launch(void* const* d_in, const int* in_sizes, int n_in,
                              void* d_out, int out_size)
{
    // Exact float64 replication of the reference _RESOLUTIONS computation.
    ResArr res;
    double b = exp((log(512.0) - log(16.0)) / 15.0);
    for (int l = 0; l < LEVELS; ++l) {
        double pw;
        if (l == 0)      pw = 1.0;
        else if (l == 1) pw = b;
        else             pw = pow(b, (double)l);
        res.r[l] = (float)floor(16.0 * pw);
    }

    const float2* x      = (const float2*)d_in[0];
    const float2* tables = (const float2*)d_in[1];
    float*        out    = (float*)d_out;

    zero_hist_kernel<<<NBUCKETS / THREADS, THREADS>>>();
    hist_kernel<<<NPTS / THREADS, THREADS>>>(x);
    scan_kernel<<<1, SCAN_THREADS>>>();
    scatter_kernel<<<NPTS / THREADS, THREADS>>>(x);
    hashenc_kernel<<<NPTS / THREADS, THREADS>>>(tables, out, res);
}

// round 4
// speedup vs baseline: 1.9618x; 1.9618x over previous
#include <cuda_runtime.h>
#include <math.h>

#define LEVELS 16
#define TABLE_SIZE 524288
#define HMASK (TABLE_SIZE - 1)
#define NPTS 1048576
#define PRIME 2654435761u
#define THREADS 256
#define NBUCKETS 65536           // 256 x 256 Morton buckets, ~16 pts each
#define SCAN_BLK 1024
#define NSCANBLK (NBUCKETS / SCAN_BLK)   // 64

struct ResArr { float r[LEVELS]; };

// Scratch (__device__ globals: the sanctioned no-allocation path)
__device__ int    d_hist[NBUCKETS];
__device__ int    d_offs[NBUCKETS];
__device__ int    d_bsum[NSCANBLK];
__device__ int    d_bbase[NSCANBLK];
__device__ int    d_perm[NPTS];
__device__ float2 d_sxy[NPTS];

__device__ __forceinline__ unsigned expand8(unsigned v) {
    v = (v | (v << 4)) & 0x0F0Fu;
    v = (v | (v << 2)) & 0x3333u;
    v = (v | (v << 1)) & 0x5555u;
    return v;
}
__device__ __forceinline__ unsigned bucket_of(float2 p) {
    unsigned bx = (unsigned)(int)(p.x * 256.0f);
    unsigned by = (unsigned)(int)(p.y * 256.0f);
    bx = bx > 255u ? 255u : bx;
    by = by > 255u ? 255u : by;
    return expand8(bx) | (expand8(by) << 1);
}

__global__ void zero_hist_kernel() {
    int i = blockIdx.x * blockDim.x + threadIdx.x;
    d_hist[i] = 0;
}

__global__ __launch_bounds__(THREADS)
void hist_kernel(const float2* __restrict__ x) {
    int i = blockIdx.x * blockDim.x + threadIdx.x;
    atomicAdd(&d_hist[bucket_of(x[i])], 1);
}

// Per-chunk exclusive scan: 64 blocks x 1024 entries, coalesced.
__global__ __launch_bounds__(SCAN_BLK)
void scan1_kernel() {
    __shared__ int sm[SCAN_BLK];
    int t = threadIdx.x;
    int i = blockIdx.x * SCAN_BLK + t;
    int v = d_hist[i];
    sm[t] = v;
    __syncthreads();
    for (int off = 1; off < SCAN_BLK; off <<= 1) {
        int u = (t >= off) ? sm[t - off] : 0;
        __syncthreads();
        sm[t] += u;
        __syncthreads();
    }
    int incl = sm[t];
    d_offs[i] = incl - v;                 // within-chunk exclusive prefix
    if (t == SCAN_BLK - 1) d_bsum[blockIdx.x] = incl;
}

// Exclusive scan of the 64 chunk sums.
__global__ void scan2_kernel() {
    __shared__ int sm[NSCANBLK];
    int t = threadIdx.x;
    int v = d_bsum[t];
    sm[t] = v;
    __syncthreads();
    for (int off = 1; off < NSCANBLK; off <<= 1) {
        int u = (t >= off) ? sm[t - off] : 0;
        __syncthreads();
        sm[t] += u;
        __syncthreads();
    }
    d_bbase[t] = sm[t] - v;
}

__global__ __launch_bounds__(THREADS)
void scatter_kernel(const float2* __restrict__ x) {
    int i = blockIdx.x * blockDim.x + threadIdx.x;
    float2 p = x[i];
    unsigned b = bucket_of(p);
    int pos = d_bbase[b >> 10] + atomicAdd(&d_offs[b], 1);
    d_perm[pos] = i;
    d_sxy[pos] = p;
}

__device__ __forceinline__ void level_gather(
    const float2* __restrict__ t, float r, float px, float py,
    float& a0, float& a1)
{
    float sx = px * r;
    float sy = py * r;
    float gxf = floorf(sx);
    float gyf = floorf(sy);
    float fx = sx - gxf;
    float fy = sy - gyf;
    float ox = 1.0f - fx;
    float oy = 1.0f - fy;

    unsigned gx = (unsigned)(int)gxf;
    unsigned gy = (unsigned)(int)gyf;
    unsigned hy0 = gy * PRIME;
    unsigned hy1 = hy0 + PRIME;

    unsigned i00 = ( gx       ^ hy0) & HMASK;
    unsigned i01 = ( gx       ^ hy1) & HMASK;
    unsigned i10 = ((gx + 1u) ^ hy0) & HMASK;
    unsigned i11 = ((gx + 1u) ^ hy1) & HMASK;

    const float4* t4 = reinterpret_cast<const float4*>(t);
    float4 q0 = __ldg(t4 + (i00 >> 1));   // covers {i00&~1, i00|1}
    float4 q1 = __ldg(t4 + (i01 >> 1));

    bool hi0 = (i00 & 1u) != 0u;
    bool hi1 = (i01 & 1u) != 0u;

    float2 f00 = hi0 ? make_float2(q0.z, q0.w) : make_float2(q0.x, q0.y);
    float2 f01 = hi1 ? make_float2(q1.z, q1.w) : make_float2(q1.x, q1.y);
    float2 f10 = hi0 ? make_float2(q0.x, q0.y) : make_float2(q0.z, q0.w);
    float2 f11 = hi1 ? make_float2(q1.x, q1.y) : make_float2(q1.z, q1.w);

    if (gx & 1u) {   // odd gx: x+1 corner isn't the pair partner
        f10 = __ldg(t + i10);
        f11 = __ldg(t + i11);
    }

    float w00 = fx * fy;
    float w10 = ox * fy;
    float w01 = fx * oy;
    float w11 = ox * oy;

    a0 = (w00 * f00.x + w10 * f10.x) + (w01 * f01.x + w11 * f11.x);
    a1 = (w00 * f00.y + w10 * f10.y) + (w01 * f01.y + w11 * f11.y);
}

__global__ __launch_bounds__(THREADS)
void hashenc_kernel(const float2* __restrict__ tables,
                    float* __restrict__ out,
                    ResArr res)
{
    __shared__ float sm[THREADS * 33];    // stride-33 pad: conflict-free
    int tid = threadIdx.x;
    int j = blockIdx.x * THREADS + tid;
    float2 p = d_sxy[j];

#pragma unroll
    for (int l = 0; l < LEVELS; ++l) {
        const float2* t = tables + (size_t)l * TABLE_SIZE;
        float a0, a1;
        level_gather(t, res.r[l], p.x, p.y, a0, a1);
        sm[tid * 33 + l]      = a0;       // out layout: [f*16 + l]
        sm[tid * 33 + 16 + l] = a1;
    }
    __syncthreads();

    // Warp-cooperative row writes: lane-per-float, 128B coalesced per row.
    int lane = tid & 31;
    int w    = tid >> 5;
    int base = blockIdx.x * THREADS;
    for (int r = w; r < THREADS; r += THREADS / 32) {
        int n = d_perm[base + r];                 // broadcast load
        out[(size_t)n * 32 + lane] = sm[r * 33 + lane];
    }
}

extern "C" void kernel_launch(void* const* d_in, const int* in_sizes, int n_in,
                              void* d_out, int out_size)
{
    // Exact float64 replication of the reference _RESOLUTIONS computation.
    ResArr res;
    double b = exp((log(512.0) - log(16.0)) / 15.0);
    for (int l = 0; l < LEVELS; ++l) {
        double pw;
        if (l == 0)      pw = 1.0;
        else if (l == 1) pw = b;
        else             pw = pow(b, (double)l);
        res.r[l] = (float)floor(16.0 * pw);
    }

    const float2* x      = (const float2*)d_in[0];
    const float2* tables = (const float2*)d_in[1];
    float*        out    = (float*)d_out;

    zero_hist_kernel<<<NBUCKETS / THREADS, THREADS>>>();
    hist_kernel<<<NPTS / THREADS, THREADS>>>(x);
    scan1_kernel<<<NSCANBLK, SCAN_BLK>>>();
    scan2_kernel<<<1, NSCANBLK>>>();
    scatter_kernel<<<NPTS / THREADS, THREADS>>>(x);
    hashenc_kernel<<<NPTS / THREADS, THREADS>>>(tables, out, res);
}